// round 9
// baseline (speedup 1.0000x reference)
#include <cuda_runtime.h>
#include <cuda_bf16.h>
#include <cstdint>

#define NBLK 128
#define NTHR 256
typedef unsigned u32;
typedef unsigned long long u64;

// -------- device scratch --------
__device__ float d_XP[(size_t)64 * 512 * 3072];   // x-projections (+bias) [b*512+s][3072]
__device__ float d_hF[2][1024 * 64];              // h fp32 [col][b], double buffered
__device__ float d_z[1024 * 64];                  // z fp32 [col][b]
__device__ unsigned short d_hHi[64 * 1024], d_hLo[64 * 1024];    // h split bf16 [b][k]
__device__ unsigned short d_rhHi[64 * 1024], d_rhLo[64 * 1024];  // r*h split bf16 [b][k]
__device__ unsigned d_count;

// smem offsets in u16 units
#define WAHI 0
#define WALO 16512
#define WBHI 33024
#define WBLO 49536
#define STH0 66048
#define STL0 74752
#define STH1 83456
#define STL1 92160
#define SMEM_BYTES (100864 * 2)

// -------- helpers --------
__device__ __forceinline__ u64 dup2(float x){u64 r;asm("mov.b64 %0,{%1,%1};":"=l"(r):"f"(x));return r;}
__device__ __forceinline__ void fma2(u64&a,u64 x,u64 y){asm("fma.rn.f32x2 %0,%1,%2,%0;":"+l"(a):"l"(x),"l"(y));}
__device__ __forceinline__ float2 unp2(u64 v){float2 f;asm("mov.b64 {%0,%1},%2;":"=f"(f.x),"=f"(f.y):"l"(v));return f;}
__device__ __forceinline__ void lds128(u64&a,u64&b,unsigned ad){asm volatile("ld.shared.v2.u64 {%0,%1},[%2];":"=l"(a),"=l"(b):"r"(ad));}
__device__ __forceinline__ float sigmoidf(float x){return 1.f/(1.f+__expf(-x));}

__device__ __forceinline__ void mma_bf16(float* c,const u32* a,const u32* b){
    asm volatile("mma.sync.aligned.m16n8k16.row.col.f32.bf16.bf16.f32 "
        "{%0,%1,%2,%3},{%4,%5,%6,%7},{%8,%9},{%0,%1,%2,%3};"
        : "+f"(c[0]),"+f"(c[1]),"+f"(c[2]),"+f"(c[3])
        : "r"(a[0]),"r"(a[1]),"r"(a[2]),"r"(a[3]),"r"(b[0]),"r"(b[1]));
}
__device__ __forceinline__ unsigned short bfhi(float x){
    return __bfloat16_as_ushort(__float2bfloat16(x));
}
__device__ __forceinline__ unsigned short bflo(float x){
    float h=__bfloat162float(__float2bfloat16(x));
    return __bfloat16_as_ushort(__float2bfloat16(x-h));
}

__device__ __forceinline__ void gridbar(){
    __syncthreads();
    if(threadIdx.x==0){
        __threadfence();
        unsigned a=atomicAdd(&d_count,1u);
        unsigned tg=a-(a&(NBLK-1))+NBLK,cur;
        do{asm volatile("ld.acquire.gpu.u32 %0,[%1];":"=r"(cur):"l"(&d_count));}while((int)(cur-tg)<0);
    }
    __syncthreads();
}

// -------- xproj (fp32, proven) --------
__global__ void __launch_bounds__(256) xproj_kernel(
    const float* __restrict__ x,
    const float* __restrict__ Wxz,const float* __restrict__ Wxr,const float* __restrict__ Wxh,
    const float* __restrict__ bz,const float* __restrict__ br,const float* __restrict__ bh){
    __shared__ float As[64*68],Bs[64*68];
    const int tid=threadIdx.x,ct=blockIdx.x,rt=blockIdx.y,wsel=ct>>4;
    const float* W=(wsel==0)?Wxz:((wsel==1)?Wxr:Wxh);
    const float* bias=(wsel==0)?bz:((wsel==1)?br:bh);
    const int colbase=(ct&15)*64,row0=rt*64,r4=(tid>>4)*4,c4=(tid&15)*4;
    u64 acc[4][2]={};
    for(int k0=0;k0<256;k0+=64){
        __syncthreads();
#pragma unroll
        for(int i=0;i<4;i++){int q=tid+i*256,rr=q>>4,kq=q&15;
            *(float4*)&As[rr*68+kq*4]=*(const float4*)&x[(size_t)(row0+rr)*256+k0+kq*4];}
#pragma unroll
        for(int i=0;i<4;i++){int q=tid+i*256,kk=q>>4,cq=q&15;
            *(float4*)&Bs[kk*68+cq*4]=*(const float4*)&W[(size_t)(k0+kk)*1024+colbase+cq*4];}
        __syncthreads();
        unsigned bs=(unsigned)__cvta_generic_to_shared(&Bs[c4]);
#pragma unroll 8
        for(int kk=0;kk<64;kk++){
            u64 bL,bH;lds128(bL,bH,bs+kk*68*4);
#pragma unroll
            for(int i=0;i<4;i++){u64 ad=dup2(As[(r4+i)*68+kk]);fma2(acc[i][0],ad,bL);fma2(acc[i][1],ad,bH);}
        }
    }
    float4 bb=*(const float4*)&bias[colbase+c4];
#pragma unroll
    for(int i=0;i<4;i++){
        float2 lo=unp2(acc[i][0]),hi=unp2(acc[i][1]);
        *(float4*)&d_XP[(size_t)(row0+r4+i)*3072+ct*64+c4]=make_float4(lo.x+bb.x,lo.y+bb.y,hi.x+bb.z,hi.y+bb.w);
    }
}

// -------- full-K split-bf16 GEMM over resident weights --------
// A = weights [16 cols][1032 k] hi/lo (smem resident, k advances with chunk!),
// B = state [64 b][k] (global, streamed in 128-k double-buffered chunks),
// C = out[4]: (g,be),(g,bo),(g+8,be),(g+8,bo).
__device__ __forceinline__ void gemm_full(
    const unsigned short* __restrict__ srcH,const unsigned short* __restrict__ srcL,
    unsigned short* sm,int wh,int wl,int tid,int g,int t2,int b0,float out[4])
{
    float acc[6][4];
#pragma unroll
    for(int i=0;i<6;i++)
#pragma unroll
    for(int q=0;q<4;q++)acc[i][q]=0.f;

    uint4 rh[4],rl[4];
#pragma unroll
    for(int i=0;i<4;i++){int idx=tid+i*NTHR,b=idx>>4,ko=(idx&15)*8;
        rh[i]=__ldcg((const uint4*)&srcH[(size_t)b*1024+ko]);
        rl[i]=__ldcg((const uint4*)&srcL[(size_t)b*1024+ko]);}
#pragma unroll
    for(int i=0;i<4;i++){int idx=tid+i*NTHR,b=idx>>4,ko=(idx&15)*8;
        *(uint4*)&sm[STH0+b*136+ko]=rh[i];
        *(uint4*)&sm[STL0+b*136+ko]=rl[i];}
    __syncthreads();
#pragma unroll 1
    for(int c=0;c<8;c++){
        if(c<7){int k0=(c+1)*128;
#pragma unroll
            for(int i=0;i<4;i++){int idx=tid+i*NTHR,b=idx>>4,ko=(idx&15)*8;
                rh[i]=__ldcg((const uint4*)&srcH[(size_t)b*1024+k0+ko]);
                rl[i]=__ldcg((const uint4*)&srcL[(size_t)b*1024+k0+ko]);}}
        const int sh=(c&1)?STH1:STH0, sl=(c&1)?STL1:STL0;
        const int brow=(b0+g)*136;
        const int wk0=c*128;   // weight k advances with chunk (R7 bug fix)
#pragma unroll
        for(int ks=0;ks<8;ks++){
            int kk=ks*16+t2;        // chunk-local k (state)
            int kw=wk0+kk;          // global k (weights)
            u32 ah[4],al[4],bh[2],bl[2];
            ah[0]=*(const u32*)&sm[wh+g*1032+kw];
            ah[1]=*(const u32*)&sm[wh+(g+8)*1032+kw];
            ah[2]=*(const u32*)&sm[wh+g*1032+kw+8];
            ah[3]=*(const u32*)&sm[wh+(g+8)*1032+kw+8];
            al[0]=*(const u32*)&sm[wl+g*1032+kw];
            al[1]=*(const u32*)&sm[wl+(g+8)*1032+kw];
            al[2]=*(const u32*)&sm[wl+g*1032+kw+8];
            al[3]=*(const u32*)&sm[wl+(g+8)*1032+kw+8];
            bh[0]=*(const u32*)&sm[sh+brow+kk];
            bh[1]=*(const u32*)&sm[sh+brow+kk+8];
            bl[0]=*(const u32*)&sm[sl+brow+kk];
            bl[1]=*(const u32*)&sm[sl+brow+kk+8];
            int p=(ks&1)*3;
            mma_bf16(acc[p+0],ah,bh);
            mma_bf16(acc[p+1],ah,bl);
            mma_bf16(acc[p+2],al,bh);
        }
        if(c<7){
            const int dh=(c&1)?STH0:STH1, dl=(c&1)?STL0:STL1;
#pragma unroll
            for(int i=0;i<4;i++){int idx=tid+i*NTHR,b=idx>>4,ko=(idx&15)*8;
                *(uint4*)&sm[dh+b*136+ko]=rh[i];
                *(uint4*)&sm[dl+b*136+ko]=rl[i];}}
        __syncthreads();
    }
#pragma unroll
    for(int q=0;q<4;q++)
        out[q]=((acc[0][q]+acc[3][q])+(acc[1][q]+acc[4][q]))+(acc[2][q]+acc[5][q]);
}

// -------- persistent GRU: full-K per block, batch-split warps, 2 barriers/step --------
__global__ void __launch_bounds__(NTHR,1) gru_kernel(
    const float* __restrict__ Whz,const float* __restrict__ Whr,const float* __restrict__ Whh){
    extern __shared__ unsigned short sm[];
    const int tid=threadIdx.x,bid=blockIdx.x,lane=tid&31;
    const int g=lane>>2,t2=(lane&3)*2,b0=(tid>>5)*8;

    // ---- resident weights: WA 16 cols of [Whz|Whr], WB 8 cols of Whh (+8 zero pad) ----
#pragma unroll 8
    for(int i=0;i<64;i++){
        int idx=tid+i*NTHR,c=idx&15,k=idx>>4;
        float w=(bid<64)?__ldg(&Whz[(size_t)k*1024+bid*16+c])
                        :__ldg(&Whr[(size_t)k*1024+(bid-64)*16+c]);
        sm[WAHI+c*1032+k]=bfhi(w);
        sm[WALO+c*1032+k]=bflo(w);
    }
#pragma unroll 8
    for(int i=0;i<64;i++){
        int idx=tid+i*NTHR,c=idx&15,k=idx>>4;
        float w=(c<8)?__ldg(&Whh[(size_t)k*1024+bid*8+c]):0.f;
        sm[WBHI+c*1032+k]=bfhi(w);
        sm[WBLO+c*1032+k]=bflo(w);
    }
    // ---- zero h0 state ----
    {
        int gid=bid*NTHR+tid;
        ((float2*)d_hF[0])[gid]=make_float2(0.f,0.f);
        ((u32*)d_hHi)[gid]=0;((u32*)d_hLo)[gid]=0;
    }
    gridbar();

    const int colA0=bid*16+g,colA1=colA0+8;
    const int colB=bid*8+g;
    const int be=b0+t2,bo=be+1;

    for(int s=0;s<512;s++){
        const int cur=s&1,nxt=cur^1;
        // ---- prefetch epilogue-A operands ----
        float xp00=__ldg(&d_XP[((size_t)be*512+s)*3072+colA0]);
        float xp01=__ldg(&d_XP[((size_t)bo*512+s)*3072+colA0]);
        float xp10=__ldg(&d_XP[((size_t)be*512+s)*3072+colA1]);
        float xp11=__ldg(&d_XP[((size_t)bo*512+s)*3072+colA1]);
        float h00=0.f,h01=0.f,h10=0.f,h11=0.f;
        if(bid>=64){
            int cp0=colA0-1024,cp1=colA1-1024;
            h00=__ldcg(&d_hF[cur][cp0*64+be]);
            h01=__ldcg(&d_hF[cur][cp0*64+bo]);
            h10=__ldcg(&d_hF[cur][cp1*64+be]);
            h11=__ldcg(&d_hF[cur][cp1*64+bo]);
        }
        // ---- phase A: z / r preactivations over full K ----
        float oa[4];
        gemm_full(d_hHi,d_hLo,sm,WAHI,WALO,tid,g,t2,b0,oa);
        {
            float v00=sigmoidf(oa[0]+xp00),v01=sigmoidf(oa[1]+xp01);
            float v10=sigmoidf(oa[2]+xp10),v11=sigmoidf(oa[3]+xp11);
            if(bid<64){
                d_z[colA0*64+be]=v00; d_z[colA0*64+bo]=v01;
                d_z[colA1*64+be]=v10; d_z[colA1*64+bo]=v11;
            }else{
                int cp0=colA0-1024,cp1=colA1-1024;
                float r00=v00*h00,r01=v01*h01,r10=v10*h10,r11=v11*h11;
                d_rhHi[(size_t)be*1024+cp0]=bfhi(r00); d_rhLo[(size_t)be*1024+cp0]=bflo(r00);
                d_rhHi[(size_t)bo*1024+cp0]=bfhi(r01); d_rhLo[(size_t)bo*1024+cp0]=bflo(r01);
                d_rhHi[(size_t)be*1024+cp1]=bfhi(r10); d_rhLo[(size_t)be*1024+cp1]=bflo(r10);
                d_rhHi[(size_t)bo*1024+cp1]=bfhi(r11); d_rhLo[(size_t)bo*1024+cp1]=bflo(r11);
            }
        }
        gridbar();
        // ---- prefetch epilogue-B operands ----
        float xq0=__ldg(&d_XP[((size_t)be*512+s)*3072+2048+colB]);
        float xq1=__ldg(&d_XP[((size_t)bo*512+s)*3072+2048+colB]);
        float z0=__ldcg(&d_z[colB*64+be]);
        float z1=__ldcg(&d_z[colB*64+bo]);
        float hb0=__ldcg(&d_hF[cur][colB*64+be]);
        float hb1=__ldcg(&d_hF[cur][colB*64+bo]);
        // ---- phase B: n preactivation over full K ----
        float ob[4];
        gemm_full(d_rhHi,d_rhLo,sm,WBHI,WBLO,tid,g,t2,b0,ob);
        {
            float n0=tanhf(ob[0]+xq0),n1=tanhf(ob[1]+xq1);
            float hn0=(1.f-z0)*hb0+z0*n0;
            float hn1=(1.f-z1)*hb1+z1*n1;
            d_hF[nxt][colB*64+be]=hn0;
            d_hF[nxt][colB*64+bo]=hn1;
            d_hHi[(size_t)be*1024+colB]=bfhi(hn0); d_hLo[(size_t)be*1024+colB]=bflo(hn0);
            d_hHi[(size_t)bo*1024+colB]=bfhi(hn1); d_hLo[(size_t)bo*1024+colB]=bflo(hn1);
        }
        gridbar();
    }
}

// -------- head: out[b][o] = sum_k hF[0][k][b]*Wf[k][o] + bf[o] --------
__global__ void head_kernel(const float* __restrict__ Wf,const float* __restrict__ bf,float* __restrict__ out){
    const int b=blockIdx.x,o=threadIdx.x;
    const float* h=d_hF[0];   // after 512 steps final h is in buffer 0
    float acc=bf[o];
#pragma unroll 8
    for(int k=0;k<1024;k++)acc+=h[k*64+b]*Wf[(size_t)k*256+o];
    out[b*256+o]=acc;
}

extern "C" void kernel_launch(void* const* d_in,const int* in_sizes,int n_in,
                              void* d_out,int out_size){
    const float* x  =(const float*)d_in[0];
    const float* Wxz=(const float*)d_in[1];
    const float* Whz=(const float*)d_in[2];
    const float* Wxr=(const float*)d_in[3];
    const float* Whr=(const float*)d_in[4];
    const float* Wxh=(const float*)d_in[5];
    const float* Whh=(const float*)d_in[6];
    const float* bz =(const float*)d_in[7];
    const float* br =(const float*)d_in[8];
    const float* bh =(const float*)d_in[9];
    const float* Wf =(const float*)d_in[10];
    const float* bf =(const float*)d_in[11];
    float* out=(float*)d_out;

    dim3 gx(48,512);
    xproj_kernel<<<gx,256>>>(x,Wxz,Wxr,Wxh,bz,br,bh);
    cudaFuncSetAttribute(gru_kernel,cudaFuncAttributeMaxDynamicSharedMemorySize,SMEM_BYTES);
    gru_kernel<<<NBLK,NTHR,SMEM_BYTES>>>(Whz,Whr,Whh);
    head_kernel<<<64,256>>>(Wf,bf,out);
}

// round 10
// speedup vs baseline: 1.2593x; 1.2593x over previous
#include <cuda_runtime.h>
#include <cuda_bf16.h>
#include <cstdint>

#define NBLK 128
#define NTHR 256
typedef unsigned u32;
typedef unsigned long long u64;

// -------- device scratch --------
__device__ float d_XP[(size_t)64 * 512 * 3072];   // x-projections (+bias) [b*512+s][3072]
__device__ float d_hF[2][1024 * 64];              // h fp32 [col][b], double buffered
__device__ unsigned short d_hHi[64 * 1024], d_hLo[64 * 1024];    // h split bf16 [b][k]
__device__ unsigned short d_rhHi[64 * 1024], d_rhLo[64 * 1024];  // r*h split bf16 [b][k]
__device__ float d_pA[(size_t)8 * 2048 * 64];     // phase-A partials [p][col][b] (z:0-1023, r:1024-2047)
__device__ float d_pB[(size_t)16 * 1024 * 64];    // phase-B partials [p][col][b]
__device__ unsigned d_count;

// -------- helpers --------
__device__ __forceinline__ u64 dup2(float x){u64 r;asm("mov.b64 %0,{%1,%1};":"=l"(r):"f"(x));return r;}
__device__ __forceinline__ void fma2(u64&a,u64 x,u64 y){asm("fma.rn.f32x2 %0,%1,%2,%0;":"+l"(a):"l"(x),"l"(y));}
__device__ __forceinline__ float2 unp2(u64 v){float2 f;asm("mov.b64 {%0,%1},%2;":"=f"(f.x),"=f"(f.y):"l"(v));return f;}
__device__ __forceinline__ void lds128(u64&a,u64&b,unsigned ad){asm volatile("ld.shared.v2.u64 {%0,%1},[%2];":"=l"(a),"=l"(b):"r"(ad));}
__device__ __forceinline__ float sigmoidf(float x){return 1.f/(1.f+__expf(-x));}

__device__ __forceinline__ void mma_bf16(float* c,const u32* a,const u32* b){
    asm volatile("mma.sync.aligned.m16n8k16.row.col.f32.bf16.bf16.f32 "
        "{%0,%1,%2,%3},{%4,%5,%6,%7},{%8,%9},{%0,%1,%2,%3};"
        : "+f"(c[0]),"+f"(c[1]),"+f"(c[2]),"+f"(c[3])
        : "r"(a[0]),"r"(a[1]),"r"(a[2]),"r"(a[3]),"r"(b[0]),"r"(b[1]));
}
__device__ __forceinline__ unsigned short bfhi(float x){
    return __bfloat16_as_ushort(__float2bfloat16(x));
}
__device__ __forceinline__ unsigned short bflo(float x){
    float h=__bfloat162float(__float2bfloat16(x));
    return __bfloat16_as_ushort(__float2bfloat16(x-h));
}

// release-atomic grid barrier (fence folded into the atomic)
__device__ __forceinline__ void gridbar(){
    __syncthreads();
    if(threadIdx.x==0){
        unsigned a;
        asm volatile("atom.add.release.gpu.u32 %0,[%1],%2;"
                     :"=r"(a):"l"(&d_count),"r"(1u):"memory");
        unsigned tg=a-(a&(NBLK-1))+NBLK,cur;
        do{asm volatile("ld.acquire.gpu.u32 %0,[%1];":"=r"(cur):"l"(&d_count));}while((int)(cur-tg)<0);
    }
    __syncthreads();
}

// -------- xproj (fp32, proven) --------
__global__ void __launch_bounds__(256) xproj_kernel(
    const float* __restrict__ x,
    const float* __restrict__ Wxz,const float* __restrict__ Wxr,const float* __restrict__ Wxh,
    const float* __restrict__ bz,const float* __restrict__ br,const float* __restrict__ bh){
    __shared__ float As[64*68],Bs[64*68];
    const int tid=threadIdx.x,ct=blockIdx.x,rt=blockIdx.y,wsel=ct>>4;
    const float* W=(wsel==0)?Wxz:((wsel==1)?Wxr:Wxh);
    const float* bias=(wsel==0)?bz:((wsel==1)?br:bh);
    const int colbase=(ct&15)*64,row0=rt*64,r4=(tid>>4)*4,c4=(tid&15)*4;
    u64 acc[4][2]={};
    for(int k0=0;k0<256;k0+=64){
        __syncthreads();
#pragma unroll
        for(int i=0;i<4;i++){int q=tid+i*256,rr=q>>4,kq=q&15;
            *(float4*)&As[rr*68+kq*4]=*(const float4*)&x[(size_t)(row0+rr)*256+k0+kq*4];}
#pragma unroll
        for(int i=0;i<4;i++){int q=tid+i*256,kk=q>>4,cq=q&15;
            *(float4*)&Bs[kk*68+cq*4]=*(const float4*)&W[(size_t)(k0+kk)*1024+colbase+cq*4];}
        __syncthreads();
        unsigned bs=(unsigned)__cvta_generic_to_shared(&Bs[c4]);
#pragma unroll 8
        for(int kk=0;kk<64;kk++){
            u64 bL,bH;lds128(bL,bH,bs+kk*68*4);
#pragma unroll
            for(int i=0;i<4;i++){u64 ad=dup2(As[(r4+i)*68+kk]);fma2(acc[i][0],ad,bL);fma2(acc[i][1],ad,bH);}
        }
    }
    float4 bb=*(const float4*)&bias[colbase+c4];
#pragma unroll
    for(int i=0;i<4;i++){
        float2 lo=unp2(acc[i][0]),hi=unp2(acc[i][1]);
        *(float4*)&d_XP[(size_t)(row0+r4+i)*3072+ct*64+c4]=make_float4(lo.x+bb.x,lo.y+bb.y,hi.x+bb.z,hi.y+bb.w);
    }
}

// -------- persistent GRU: HMMA split-bf16, K split across blocks (R6 structure) --------
// smem (u16 units): WA hi/lo [64][264], WB hi/lo [64][136], ST hi/lo [64][264]
#define WAHI 0
#define WALO 16896
#define WBHI 33792
#define WBLO 42496
#define STHI 51200
#define STLO 68096
#define SMEM_BYTES (84992*2)

__global__ void __launch_bounds__(NTHR,1) gru_kernel(
    const float* __restrict__ Whz,const float* __restrict__ Whr,const float* __restrict__ Whh){
    extern __shared__ unsigned short sm[];
    const int tid=threadIdx.x,bid=blockIdx.x,wid=tid>>5,lane=tid&31;
    const int cg=bid&31, kg=bid>>5;    // phase A: 32 col-groups x 4 k-groups(256)
    const int cgB=bid&15,kgB=bid>>4;   // phase B: 16 col-groups x 8 k-groups(128)

    // ---- load resident weight slices (split bf16, [col][k]+pad) ----
    {
        const int colg0=cg*64;
        const float* W=(colg0<1024)?(Whz+colg0):(Whr+colg0-1024);
#pragma unroll 4
        for(int i=0;i<64;i++){
            int idx=tid+i*NTHR,col=idx&63,k=idx>>6;
            float w=__ldg(&W[(size_t)(kg*256+k)*1024+col]);
            sm[WAHI+col*264+k]=bfhi(w);
            sm[WALO+col*264+k]=bflo(w);
        }
#pragma unroll 4
        for(int i=0;i<32;i++){
            int idx=tid+i*NTHR,col=idx&63,k=idx>>6;
            float w=__ldg(&Whh[(size_t)(kgB*128+k)*1024+cgB*64+col]);
            sm[WBHI+col*136+k]=bfhi(w);
            sm[WBLO+col*136+k]=bflo(w);
        }
    }
    // ---- zero h0 state ----
    {
        int gid=bid*NTHR+tid;
        ((float2*)d_hF[0])[gid]=make_float2(0.f,0.f);
        ((u32*)d_hHi)[gid]=0;((u32*)d_hLo)[gid]=0;
    }
    gridbar();

    const int mw=wid&1,nw=(wid>>1)&1,kw=wid>>2;
    const int g=lane>>2,tk=(lane&3)*2;
    const int ecol=bid*8+wid;     // epilogue col (0..1023), same both phases
    const int eb=lane*2;          // epilogue: batch pair

    for(int s=0;s<512;s++){
        const int cur=s&1,nxt=cur^1;
        // prefetch epilogue-A operands (r-col = 1024+ecol)
        float xpr0=__ldg(&d_XP[((size_t)eb*512+s)*3072+1024+ecol]);
        float xpr1=__ldg(&d_XP[((size_t)(eb+1)*512+s)*3072+1024+ecol]);
        float2 hA=__ldcg((const float2*)&d_hF[cur][ecol*64+eb]);
        // ---- stage h slice (kg*256) ----
#pragma unroll
        for(int i=0;i<8;i++){
            int u=tid+i*NTHR,b=u>>5,ko=u&31;
            uint4 v=__ldcg((const uint4*)&d_hHi[(size_t)b*1024+kg*256+ko*8]);
            *(uint4*)&sm[STHI+b*264+ko*8]=v;
            uint4 w=__ldcg((const uint4*)&d_hLo[(size_t)b*1024+kg*256+ko*8]);
            *(uint4*)&sm[STLO+b*264+ko*8]=w;
        }
        __syncthreads();
        // ---- phase A MMA: warp m32n32, k-slice kw*128 ----
        float c[2][4][4];
#pragma unroll
        for(int mt=0;mt<2;mt++)
#pragma unroll
        for(int nt=0;nt<4;nt++)
#pragma unroll
        for(int q=0;q<4;q++)c[mt][nt][q]=0.f;
#pragma unroll 1
        for(int i=0;i<8;i++){
            int kk=kw*128+i*16+tk;
            u32 ah[2][4],al[2][4],bh[4][2],bl[4][2];
#pragma unroll
            for(int mt=0;mt<2;mt++){
                int r=mw*32+mt*16+g;
                ah[mt][0]=*(const u32*)&sm[WAHI+r*264+kk];
                ah[mt][1]=*(const u32*)&sm[WAHI+(r+8)*264+kk];
                ah[mt][2]=*(const u32*)&sm[WAHI+r*264+kk+8];
                ah[mt][3]=*(const u32*)&sm[WAHI+(r+8)*264+kk+8];
                al[mt][0]=*(const u32*)&sm[WALO+r*264+kk];
                al[mt][1]=*(const u32*)&sm[WALO+(r+8)*264+kk];
                al[mt][2]=*(const u32*)&sm[WALO+r*264+kk+8];
                al[mt][3]=*(const u32*)&sm[WALO+(r+8)*264+kk+8];
            }
#pragma unroll
            for(int nt=0;nt<4;nt++){
                int b=nw*32+nt*8+g;
                bh[nt][0]=*(const u32*)&sm[STHI+b*264+kk];
                bh[nt][1]=*(const u32*)&sm[STHI+b*264+kk+8];
                bl[nt][0]=*(const u32*)&sm[STLO+b*264+kk];
                bl[nt][1]=*(const u32*)&sm[STLO+b*264+kk+8];
            }
#pragma unroll
            for(int mt=0;mt<2;mt++)
#pragma unroll
            for(int nt=0;nt<4;nt++){
                mma_bf16(c[mt][nt],ah[mt],bh[nt]);
                mma_bf16(c[mt][nt],ah[mt],bl[nt]);
                mma_bf16(c[mt][nt],al[mt],bh[nt]);
            }
        }
        {
            int p=kg*2+kw;
#pragma unroll
            for(int mt=0;mt<2;mt++){
                int col=cg*64+mw*32+mt*16+g;
#pragma unroll
                for(int nt=0;nt<4;nt++){
                    int b=nw*32+nt*8+tk;
                    *(float2*)&d_pA[((size_t)p*2048+col)*64+b]=make_float2(c[mt][nt][0],c[mt][nt][1]);
                    *(float2*)&d_pA[((size_t)p*2048+col+8)*64+b]=make_float2(c[mt][nt][2],c[mt][nt][3]);
                }
            }
        }
        gridbar();
        // ---- epilogue A: sum 8 r-partials -> sigmoid*h -> rh (uniform across blocks) ----
        {
            float s0=0.f,s1=0.f;
#pragma unroll
            for(int p=0;p<8;p++){
                float2 v=__ldcg((const float2*)&d_pA[((size_t)p*2048+1024+ecol)*64+eb]);
                s0+=v.x;s1+=v.y;
            }
            float r0=sigmoidf(s0+xpr0)*hA.x;
            float r1=sigmoidf(s1+xpr1)*hA.y;
            d_rhHi[(size_t)eb*1024+ecol]=bfhi(r0); d_rhLo[(size_t)eb*1024+ecol]=bflo(r0);
            d_rhHi[(size_t)(eb+1)*1024+ecol]=bfhi(r1); d_rhLo[(size_t)(eb+1)*1024+ecol]=bflo(r1);
        }
        gridbar();
        // prefetch epilogue-B operands (z-col = ecol, n-col = 2048+ecol)
        float xpz0=__ldg(&d_XP[((size_t)eb*512+s)*3072+ecol]);
        float xpz1=__ldg(&d_XP[((size_t)(eb+1)*512+s)*3072+ecol]);
        float xpn0=__ldg(&d_XP[((size_t)eb*512+s)*3072+2048+ecol]);
        float xpn1=__ldg(&d_XP[((size_t)(eb+1)*512+s)*3072+2048+ecol]);
        float2 hv=__ldcg((const float2*)&d_hF[cur][ecol*64+eb]);
        // ---- stage rh slice (kgB*128) ----
#pragma unroll
        for(int i=0;i<4;i++){
            int u=tid+i*NTHR,b=u>>4,ko=u&15;
            uint4 v=__ldcg((const uint4*)&d_rhHi[(size_t)b*1024+kgB*128+ko*8]);
            *(uint4*)&sm[STHI+b*264+ko*8]=v;
            uint4 w=__ldcg((const uint4*)&d_rhLo[(size_t)b*1024+kgB*128+ko*8]);
            *(uint4*)&sm[STLO+b*264+ko*8]=w;
        }
        __syncthreads();
        // ---- phase B MMA: warp m32n32, k-slice kw*64 ----
        float cb[2][4][4];
#pragma unroll
        for(int mt=0;mt<2;mt++)
#pragma unroll
        for(int nt=0;nt<4;nt++)
#pragma unroll
        for(int q=0;q<4;q++)cb[mt][nt][q]=0.f;
#pragma unroll 1
        for(int i=0;i<4;i++){
            int kk=kw*64+i*16+tk;
            u32 ah[2][4],al[2][4],bh[4][2],bl[4][2];
#pragma unroll
            for(int mt=0;mt<2;mt++){
                int r=mw*32+mt*16+g;
                ah[mt][0]=*(const u32*)&sm[WBHI+r*136+kk];
                ah[mt][1]=*(const u32*)&sm[WBHI+(r+8)*136+kk];
                ah[mt][2]=*(const u32*)&sm[WBHI+r*136+kk+8];
                ah[mt][3]=*(const u32*)&sm[WBHI+(r+8)*136+kk+8];
                al[mt][0]=*(const u32*)&sm[WBLO+r*136+kk];
                al[mt][1]=*(const u32*)&sm[WBLO+(r+8)*136+kk];
                al[mt][2]=*(const u32*)&sm[WBLO+r*136+kk+8];
                al[mt][3]=*(const u32*)&sm[WBLO+(r+8)*136+kk+8];
            }
#pragma unroll
            for(int nt=0;nt<4;nt++){
                int b=nw*32+nt*8+g;
                bh[nt][0]=*(const u32*)&sm[STHI+b*264+kk];
                bh[nt][1]=*(const u32*)&sm[STHI+b*264+kk+8];
                bl[nt][0]=*(const u32*)&sm[STLO+b*264+kk];
                bl[nt][1]=*(const u32*)&sm[STLO+b*264+kk+8];
            }
#pragma unroll
            for(int mt=0;mt<2;mt++)
#pragma unroll
            for(int nt=0;nt<4;nt++){
                mma_bf16(cb[mt][nt],ah[mt],bh[nt]);
                mma_bf16(cb[mt][nt],ah[mt],bl[nt]);
                mma_bf16(cb[mt][nt],al[mt],bh[nt]);
            }
        }
        {
            int p=kgB*2+kw;
#pragma unroll
            for(int mt=0;mt<2;mt++){
                int col=cgB*64+mw*32+mt*16+g;
#pragma unroll
                for(int nt=0;nt<4;nt++){
                    int b=nw*32+nt*8+tk;
                    *(float2*)&d_pB[((size_t)p*1024+col)*64+b]=make_float2(cb[mt][nt][0],cb[mt][nt][1]);
                    *(float2*)&d_pB[((size_t)p*1024+col+8)*64+b]=make_float2(cb[mt][nt][2],cb[mt][nt][3]);
                }
            }
        }
        gridbar();
        // ---- epilogue B: z from pA, n from pB, h update (uniform) ----
        {
            float z0=0.f,z1=0.f,n0=0.f,n1=0.f;
#pragma unroll
            for(int p=0;p<8;p++){
                float2 v=__ldcg((const float2*)&d_pA[((size_t)p*2048+ecol)*64+eb]);
                z0+=v.x;z1+=v.y;
            }
#pragma unroll
            for(int p=0;p<16;p++){
                float2 v=__ldcg((const float2*)&d_pB[((size_t)p*1024+ecol)*64+eb]);
                n0+=v.x;n1+=v.y;
            }
            z0=sigmoidf(z0+xpz0); z1=sigmoidf(z1+xpz1);
            n0=tanhf(n0+xpn0);    n1=tanhf(n1+xpn1);
            float h0=(1.f-z0)*hv.x+z0*n0;
            float h1=(1.f-z1)*hv.y+z1*n1;
            *(float2*)&d_hF[nxt][ecol*64+eb]=make_float2(h0,h1);
            d_hHi[(size_t)eb*1024+ecol]=bfhi(h0); d_hLo[(size_t)eb*1024+ecol]=bflo(h0);
            d_hHi[(size_t)(eb+1)*1024+ecol]=bfhi(h1); d_hLo[(size_t)(eb+1)*1024+ecol]=bflo(h1);
        }
        gridbar();
    }
}

// -------- head: out[b][o] = sum_k hF[0][k][b]*Wf[k][o] + bf[o] --------
__global__ void head_kernel(const float* __restrict__ Wf,const float* __restrict__ bf,float* __restrict__ out){
    const int b=blockIdx.x,o=threadIdx.x;
    const float* h=d_hF[0];   // after 512 steps final h is in buffer 0
    float acc=bf[o];
#pragma unroll 8
    for(int k=0;k<1024;k++)acc+=h[k*64+b]*Wf[(size_t)k*256+o];
    out[b*256+o]=acc;
}

extern "C" void kernel_launch(void* const* d_in,const int* in_sizes,int n_in,
                              void* d_out,int out_size){
    const float* x  =(const float*)d_in[0];
    const float* Wxz=(const float*)d_in[1];
    const float* Whz=(const float*)d_in[2];
    const float* Wxr=(const float*)d_in[3];
    const float* Whr=(const float*)d_in[4];
    const float* Wxh=(const float*)d_in[5];
    const float* Whh=(const float*)d_in[6];
    const float* bz =(const float*)d_in[7];
    const float* br =(const float*)d_in[8];
    const float* bh =(const float*)d_in[9];
    const float* Wf =(const float*)d_in[10];
    const float* bf =(const float*)d_in[11];
    float* out=(float*)d_out;

    dim3 gx(48,512);
    xproj_kernel<<<gx,256>>>(x,Wxz,Wxr,Wxh,bz,br,bh);
    cudaFuncSetAttribute(gru_kernel,cudaFuncAttributeMaxDynamicSharedMemorySize,SMEM_BYTES);
    gru_kernel<<<NBLK,NTHR,SMEM_BYTES>>>(Whz,Whr,Whh);
    head_kernel<<<64,256>>>(Wf,bf,out);
}